// round 8
// baseline (speedup 1.0000x reference)
#include <cuda_runtime.h>
#include <stdint.h>

#define B_ 2
#define S_ 2048
#define E_ 768
#define H_ 8
#define D_ 96
#define M_ 4096   // B*S

// scratch (no cudaMalloc allowed)
__device__ float g_Q[M_ * E_];   // [B,H,S,D]
__device__ float g_K[M_ * E_];   // [B,H,S,D] (also V — reference bug)
__device__ float g_AO[M_ * E_];  // attention output, [B,S,E]

// ---------------------------------------------------------------------------
// tf32 helpers
// ---------------------------------------------------------------------------
__device__ __forceinline__ uint32_t f2tf(float x) {
    uint32_t r;
    asm("cvt.rna.tf32.f32 %0, %1;" : "=r"(r) : "f"(x));
    return r;
}
__device__ __forceinline__ void split1(float x, uint32_t& h, uint32_t& l) {
    h = f2tf(x);
    l = f2tf(x - __uint_as_float(h));
}
__device__ __forceinline__ void mma4(float (&d)[4], uint4 a, uint2 b) {
    asm volatile(
        "mma.sync.aligned.m16n8k8.row.col.f32.tf32.tf32.f32 "
        "{%0,%1,%2,%3}, {%4,%5,%6,%7}, {%8,%9}, {%0,%1,%2,%3};"
        : "+f"(d[0]), "+f"(d[1]), "+f"(d[2]), "+f"(d[3])
        : "r"(a.x), "r"(a.y), "r"(a.z), "r"(a.w), "r"(b.x), "r"(b.y));
}

// Fragment-packed layouts:
//  A-pack (m16k8): word = ((rb*NKB + kb)*32 + lane)*4 + w
//    w=0:(lq,la) w=1:(lq+8,la) w=2:(lq,la+4) w=3:(lq+8,la+4)
//  B-pack (n8k8):  word = ((nb*NKB + kb)*32 + lane)*2 + w
//    w=0:(n=lq,k=la) w=1:(n=lq,k=la+4)

// ===========================================================================
// GEMM: C[128x64] = A[128x768] * W[768x64], TERMS-compensated tf32.
// (unchanged from R7 — passing at 244us; attention is this round's target)
// ===========================================================================
template <int TERMS>
__device__ __forceinline__ void g_store_stage(
    uint32_t* AsH, uint32_t* AsL, uint32_t* BsH, uint32_t* BsL,
    int stage, const int (&ast)[2], const int (&bst)[2],
    const float (&a)[2][4], const float (&b)[2][2])
{
    uint32_t* pAH = AsH + stage * 2048;
    uint32_t* pAL = AsL + stage * 2048;
    uint32_t* pBH = BsH + stage * 1024;
    uint32_t* pBL = BsL + stage * 1024;
    #pragma unroll
    for (int g = 0; g < 2; g++) {
        uint32_t h[4], l[4];
        #pragma unroll
        for (int w = 0; w < 4; w++) split1(a[g][w], h[w], l[w]);
        *(uint4*)(pAH + ast[g]) = make_uint4(h[0], h[1], h[2], h[3]);
        if (TERMS >= 2)
            *(uint4*)(pAL + ast[g]) = make_uint4(l[0], l[1], l[2], l[3]);
        uint32_t bh[2], bl[2];
        #pragma unroll
        for (int w = 0; w < 2; w++) split1(b[g][w], bh[w], bl[w]);
        *(uint2*)(pBH + bst[g]) = make_uint2(bh[0], bh[1]);
        if (TERMS >= 3)
            *(uint2*)(pBL + bst[g]) = make_uint2(bl[0], bl[1]);
    }
}

template <int TERMS>
__device__ __forceinline__ void gemm_acc(
    const float* __restrict__ Ag, const float* __restrict__ Wg,
    int m0, int n0,
    uint32_t* AsH, uint32_t* AsL, uint32_t* BsH, uint32_t* BsL,
    float (&acc)[2][4][4])
{
    const int tid = threadIdx.x, lane = tid & 31, wid = tid >> 5;
    const int rbb = (wid >> 1) * 2;
    const int nbb = (wid & 1) * 4;

    int aof[2][4], ast[2], bof[2][2], bst[2];
    #pragma unroll
    for (int g = 0; g < 2; g++) {
        int gg = tid + g * 256;
        int blk = gg >> 6, kb = (gg >> 5) & 1, ln = gg & 31;
        int lq = ln >> 2, la = ln & 3;
        #pragma unroll
        for (int w = 0; w < 4; w++) {
            int r = blk * 16 + lq + 8 * (w & 1);
            int k = kb * 8 + la + 4 * (w >> 1);
            aof[g][w] = r * E_ + k;
        }
        ast[g] = gg * 4;
        #pragma unroll
        for (int w = 0; w < 2; w++) {
            int n = blk * 8 + lq;
            int k = kb * 8 + la + 4 * w;
            bof[g][w] = k * E_ + n;
        }
        bst[g] = gg * 2;
    }

    const float* Ap = Ag + (size_t)m0 * E_;
    const float* Wp = Wg + n0;

    float ar[2][2][4], br[2][2][2];
    #pragma unroll
    for (int g = 0; g < 2; g++) {
        #pragma unroll
        for (int w = 0; w < 4; w++) ar[0][g][w] = Ap[aof[g][w]];
        #pragma unroll
        for (int w = 0; w < 2; w++) br[0][g][w] = Wp[bof[g][w]];
    }
    g_store_stage<TERMS>(AsH, AsL, BsH, BsL, 0, ast, bst, ar[0], br[0]);
    #pragma unroll
    for (int g = 0; g < 2; g++) {
        #pragma unroll
        for (int w = 0; w < 4; w++) ar[1][g][w] = Ap[16 + aof[g][w]];
        #pragma unroll
        for (int w = 0; w < 2; w++) br[1][g][w] = Wp[16 * E_ + bof[g][w]];
    }
    __syncthreads();

    #pragma unroll 2
    for (int c = 0; c < 48; c++) {
        const int s = c & 1;
        if (c + 2 < 48) {
            const float* Ap2 = Ap + (c + 2) * 16;
            const float* Wp2 = Wp + (size_t)(c + 2) * 16 * E_;
            #pragma unroll
            for (int g = 0; g < 2; g++) {
                #pragma unroll
                for (int w = 0; w < 4; w++) ar[s][g][w] = Ap2[aof[g][w]];
                #pragma unroll
                for (int w = 0; w < 2; w++) br[s][g][w] = Wp2[bof[g][w]];
            }
        }
        if (c + 1 < 48)
            g_store_stage<TERMS>(AsH, AsL, BsH, BsL, s ^ 1, ast, bst,
                                 ar[s ^ 1], br[s ^ 1]);

        uint32_t* pAH = AsH + s * 2048;
        uint32_t* pAL = AsL + s * 2048;
        uint32_t* pBH = BsH + s * 1024;
        uint32_t* pBL = BsL + s * 1024;
        #pragma unroll
        for (int kb = 0; kb < 2; kb++) {
            uint4 ah0 = *(const uint4*)(pAH + rbb * 256 + kb * 128 + lane * 4);
            uint4 ah1 = *(const uint4*)(pAH + (rbb + 1) * 256 + kb * 128 + lane * 4);
            uint4 al0, al1;
            if (TERMS >= 2) {
                al0 = *(const uint4*)(pAL + rbb * 256 + kb * 128 + lane * 4);
                al1 = *(const uint4*)(pAL + (rbb + 1) * 256 + kb * 128 + lane * 4);
            }
            #pragma unroll
            for (int nf = 0; nf < 4; nf++) {
                uint2 bh = *(const uint2*)(pBH + (nbb + nf) * 128 + kb * 64 + lane * 2);
                mma4(acc[0][nf], ah0, bh);
                mma4(acc[1][nf], ah1, bh);
                if (TERMS >= 2) {
                    mma4(acc[0][nf], al0, bh);
                    mma4(acc[1][nf], al1, bh);
                }
                if (TERMS >= 3) {
                    uint2 bl = *(const uint2*)(pBL + (nbb + nf) * 128 + kb * 64 + lane * 2);
                    mma4(acc[0][nf], ah0, bl);
                    mma4(acc[1][nf], ah1, bl);
                }
            }
        }
        __syncthreads();
    }
}

__global__ void __launch_bounds__(256, 2) proj_kernel(
    const float* __restrict__ X,
    const float* __restrict__ Wq, const float* __restrict__ bq,
    const float* __restrict__ Wk, const float* __restrict__ bk)
{
    __shared__ uint32_t AsH[2 * 2048], AsL[2 * 2048];
    __shared__ uint32_t BsH[2 * 1024], BsL[2 * 1024];

    const float* W    = blockIdx.z ? Wk : Wq;
    const float* bias = blockIdx.z ? bk : bq;
    float* out        = blockIdx.z ? g_K : g_Q;

    const int m0 = blockIdx.x * 128, n0 = blockIdx.y * 64;
    const int lane = threadIdx.x & 31, wid = threadIdx.x >> 5;
    const int wm = (wid >> 1) * 32, wn = (wid & 1) * 32;
    const int la = lane & 3, lq = lane >> 2;

    float acc[2][4][4];
    #pragma unroll
    for (int i = 0; i < 2; i++)
        #pragma unroll
        for (int j = 0; j < 4; j++)
            #pragma unroll
            for (int k = 0; k < 4; k++) acc[i][j][k] = 0.f;

    gemm_acc<3>(X, W, m0, n0, AsH, AsL, BsH, BsL, acc);

    #pragma unroll
    for (int mi = 0; mi < 2; mi++) {
        int r = wm + mi * 16 + lq;
        #pragma unroll
        for (int nf = 0; nf < 4; nf++) {
            int n = n0 + wn + nf * 8 + la * 2;
            int h = n / D_, d = n % D_;
            int h1 = (n + 1) / D_, d1 = (n + 1) % D_;
            #pragma unroll
            for (int rr = 0; rr < 2; rr++) {
                int m = m0 + r + rr * 8;
                int bb = m >> 11, s = m & (S_ - 1);
                size_t base = ((size_t)(bb * H_)) * S_ * D_ + (size_t)s * D_;
                out[base + (size_t)h * S_ * D_ + d]   = acc[mi][nf][rr * 2 + 0] + bias[n];
                out[base + (size_t)h1 * S_ * D_ + d1] = acc[mi][nf][rr * 2 + 1] + bias[n + 1];
            }
        }
    }
}

__global__ void __launch_bounds__(256, 2) outproj_kernel(
    const float* __restrict__ Wo, const float* __restrict__ bo,
    float* __restrict__ Y)
{
    __shared__ uint32_t AsH[2 * 2048], AsL[2 * 2048];
    __shared__ uint32_t BsH[2 * 1024], BsL[2 * 1024];

    const int m0 = blockIdx.x * 128, n0 = blockIdx.y * 64;
    const int lane = threadIdx.x & 31, wid = threadIdx.x >> 5;
    const int wm = (wid >> 1) * 32, wn = (wid & 1) * 32;
    const int la = lane & 3, lq = lane >> 2;

    float acc[2][4][4];
    #pragma unroll
    for (int i = 0; i < 2; i++)
        #pragma unroll
        for (int j = 0; j < 4; j++)
            #pragma unroll
            for (int k = 0; k < 4; k++) acc[i][j][k] = 0.f;

    gemm_acc<2>(g_AO, Wo, m0, n0, AsH, AsL, BsH, BsL, acc);

    #pragma unroll
    for (int mi = 0; mi < 2; mi++) {
        int r = wm + mi * 16 + lq;
        #pragma unroll
        for (int nf = 0; nf < 4; nf++) {
            int n = n0 + wn + nf * 8 + la * 2;
            #pragma unroll
            for (int rr = 0; rr < 2; rr++) {
                int m = m0 + r + rr * 8;
                Y[(size_t)m * E_ + n]     = acc[mi][nf][rr * 2 + 0] + bo[n];
                Y[(size_t)m * E_ + n + 1] = acc[mi][nf][rr * 2 + 1] + bo[n + 1];
            }
        }
    }
}

// ===========================================================================
// Flash attention, mma.sync tf32, V == K (reference bug), no-max softmax.
// 512 threads: warps 0-7 COMPUTE (each 16 q-rows x all 64 keys, nb=8),
// warps 8-15 LOADERS (pack K hi/lo double-buffered + V^T single-buffered).
// QK^T 3xTF32; P stays in registers (D->A fragment shuffle); PV 1xTF32.
// Per-warp O and row-sums are complete -> no cross-warp reductions.
// Smem (words): Q-pack hi/lo 2x12288 | K-pack hi/lo 2 bufs x 12288 | V^T 6144
// ===========================================================================
#define AQ_H 0
#define AQ_L 12288
#define AK_0 24576
#define AV_  49152
#define ATTN_WORDS 55296
#define ATTN_SMEM_BYTES (ATTN_WORDS * 4)   // 221,184

__global__ void __launch_bounds__(512, 1) attn_kernel()
{
    extern __shared__ uint32_t sm[];
    const int tid = threadIdx.x, lane = tid & 31, wid = tid >> 5;
    const int la = lane & 3, lq = lane >> 2;
    const int bh = blockIdx.y, qt = blockIdx.x;

    const float* Qg = g_Q + (size_t)bh * S_ * D_ + (size_t)qt * 128 * D_;
    const float* Kg = g_K + (size_t)bh * S_ * D_;

    // ---- pack Q tile (128x96) into hi/lo A-pack (all 512 threads) ----
    #pragma unroll
    for (int i = 0; i < 6; i++) {
        int gg = tid + i * 512;               // < 3072 groups
        int rb = gg / 384, rem = gg - rb * 384;
        int kb = rem >> 5, ln = rem & 31;
        int glq = ln >> 2, gla = ln & 3;
        float v[4];
        #pragma unroll
        for (int w = 0; w < 4; w++) {
            int r = rb * 16 + glq + 8 * (w & 1);
            int k = kb * 8 + gla + 4 * (w >> 1);
            v[w] = Qg[r * D_ + k];
        }
        uint32_t h[4], l[4];
        #pragma unroll
        for (int w = 0; w < 4; w++) split1(v[w], h[w], l[w]);
        *(uint4*)(sm + AQ_H + gg * 4) = make_uint4(h[0], h[1], h[2], h[3]);
        *(uint4*)(sm + AQ_L + gg * 4) = make_uint4(l[0], l[1], l[2], l[3]);
    }

    const bool loader = wid >= 8;

    int kof[12], kst[12], vof[12], vst[12];
    float vr[12][2];
    if (loader) {
        int tl = tid - 256;
        #pragma unroll
        for (int i = 0; i < 12; i++) {
            int gg = tl + i * 256;
            // K-pack group: B-frag (n=key, k=d)
            int nb = gg / 384, rem = gg - nb * 384;
            int kb = rem >> 5, ln = rem & 31;
            kof[i] = (nb * 8 + (ln >> 2)) * D_ + kb * 8 + (ln & 3);
            kst[i] = gg * 2;
            // V^T group: B-frag (n=d, k=key)
            int nbd = gg >> 8, rem2 = gg & 255;
            int kbk = rem2 >> 5, ln2 = rem2 & 31;
            vof[i] = (kbk * 8 + (ln2 & 3)) * D_ + nbd * 8 + (ln2 >> 2);
            vst[i] = gg * 2;
        }
        // prologue: K-pack tile 0 -> buf0; V elems of tile 0 -> regs
        uint32_t* KH0 = sm + AK_0;
        uint32_t* KL0 = KH0 + 6144;
        #pragma unroll
        for (int i = 0; i < 12; i++) {
            float a = Kg[kof[i]], b = Kg[kof[i] + 4];
            uint32_t h0, l0, h1, l1;
            split1(a, h0, l0);
            split1(b, h1, l1);
            *(uint2*)(KH0 + kst[i]) = make_uint2(h0, h1);
            *(uint2*)(KL0 + kst[i]) = make_uint2(l0, l1);
            vr[i][0] = Kg[vof[i]];
            vr[i][1] = Kg[vof[i] + 4 * D_];
        }
    }
    __syncthreads();

    const int rg = wid;                       // compute warps: rows rg*16..+16
    float O[12][4];
    #pragma unroll
    for (int nb = 0; nb < 12; nb++)
        #pragma unroll
        for (int r = 0; r < 4; r++) O[nb][r] = 0.f;
    float ls0 = 0.f, ls1 = 0.f;
    uint32_t pt[8][4];

    for (int kt = 0; kt < 32; kt++) {
        const int s = kt & 1;
        uint32_t* KH = sm + AK_0 + s * 12288;
        uint32_t* KL = KH + 6144;
        uint32_t* VT = sm + AV_;

        if (loader) {
            // publish V^T[kt] (PV of kt-1 finished before loop-top sync)
            #pragma unroll
            for (int i = 0; i < 12; i++)
                *(uint2*)(VT + vst[i]) =
                    make_uint2(f2tf(vr[i][0]), f2tf(vr[i][1]));
        } else {
            // S = Q K^T : 16 rows x 64 keys, 3xTF32
            float s4[8][4];
            #pragma unroll
            for (int nb = 0; nb < 8; nb++)
                #pragma unroll
                for (int r = 0; r < 4; r++) s4[nb][r] = 0.f;

            #pragma unroll
            for (int kb = 0; kb < 12; kb++) {
                uint4 ah = *(const uint4*)(sm + AQ_H + (rg * 12 + kb) * 128 + lane * 4);
                uint4 al = *(const uint4*)(sm + AQ_L + (rg * 12 + kb) * 128 + lane * 4);
                #pragma unroll
                for (int nb = 0; nb < 8; nb++) {
                    uint2 bhv = *(const uint2*)(KH + (nb * 12 + kb) * 64 + lane * 2);
                    uint2 blv = *(const uint2*)(KL + (nb * 12 + kb) * 64 + lane * 2);
                    mma4(s4[nb], ah, bhv);
                    mma4(s4[nb], al, bhv);
                    mma4(s4[nb], ah, blv);
                }
            }
            // exp (no max) -> tf32 P in registers; row sums
            #pragma unroll
            for (int nb = 0; nb < 8; nb++) {
                float p0 = __expf(s4[nb][0]);
                float p1 = __expf(s4[nb][1]);
                float p2 = __expf(s4[nb][2]);
                float p3 = __expf(s4[nb][3]);
                ls0 += p0 + p1;
                ls1 += p2 + p3;
                pt[nb][0] = f2tf(p0);
                pt[nb][1] = f2tf(p1);
                pt[nb][2] = f2tf(p2);
                pt[nb][3] = f2tf(p3);
            }
        }
        __syncthreads();   // V^T[kt] visible; compute has S in regs

        if (!loader) {
            // D->A fragment shuffle + O += P @ V (V == K)
            const int s0l = (lq << 2) + (la >> 1);
            const int s1l = s0l + 2;
            const bool odd = la & 1;
            #pragma unroll
            for (int kb = 0; kb < 8; kb++) {
                uint32_t t0 = __shfl_sync(0xffffffffu, pt[kb][0], s0l);
                uint32_t t1 = __shfl_sync(0xffffffffu, pt[kb][1], s0l);
                uint32_t t2 = __shfl_sync(0xffffffffu, pt[kb][2], s0l);
                uint32_t t3 = __shfl_sync(0xffffffffu, pt[kb][3], s0l);
                uint32_t u0 = __shfl_sync(0xffffffffu, pt[kb][0], s1l);
                uint32_t u1 = __shfl_sync(0xffffffffu, pt[kb][1], s1l);
                uint32_t u2 = __shfl_sync(0xffffffffu, pt[kb][2], s1l);
                uint32_t u3 = __shfl_sync(0xffffffffu, pt[kb][3], s1l);
                uint4 a = make_uint4(odd ? t1 : t0, odd ? t3 : t2,
                                     odd ? u1 : u0, odd ? u3 : u2);
                #pragma unroll
                for (int nb = 0; nb < 12; nb++) {
                    uint2 bv = *(const uint2*)(VT + (nb * 8 + kb) * 64 + lane * 2);
                    mma4(O[nb], a, bv);
                }
            }
        } else if (kt < 31) {
            // fetch + pack tile kt+1 (overlapped with PV)
            const float* Kn = Kg + (size_t)(kt + 1) * 64 * D_;
            uint32_t* KH2 = sm + AK_0 + (s ^ 1) * 12288;
            uint32_t* KL2 = KH2 + 6144;
            #pragma unroll
            for (int i = 0; i < 12; i++) {
                float a = Kn[kof[i]], b = Kn[kof[i] + 4];
                uint32_t h0, l0, h1, l1;
                split1(a, h0, l0);
                split1(b, h1, l1);
                *(uint2*)(KH2 + kst[i]) = make_uint2(h0, h1);
                *(uint2*)(KL2 + kst[i]) = make_uint2(l0, l1);
            }
            #pragma unroll
            for (int i = 0; i < 12; i++) {
                vr[i][0] = Kn[vof[i]];
                vr[i][1] = Kn[vof[i] + 4 * D_];
            }
        }
        __syncthreads();   // end of tile: PV done, K[kt+1] packed
    }

    if (!loader) {
        // full row sums: reduce over quad lanes (cols are quad-distributed)
        ls0 += __shfl_xor_sync(0xffffffffu, ls0, 1);
        ls0 += __shfl_xor_sync(0xffffffffu, ls0, 2);
        ls1 += __shfl_xor_sync(0xffffffffu, ls1, 1);
        ls1 += __shfl_xor_sync(0xffffffffu, ls1, 2);

        const float SCALE = 0.10206207261596577f;   // 96^-0.5
        float inv0 = SCALE / ls0, inv1 = SCALE / ls1;
        const int bb = bh >> 3, h = bh & 7;
        int r0 = qt * 128 + rg * 16 + lq;
        float* dst0 = g_AO + ((size_t)(bb * S_ + r0)) * E_ + h * D_;
        float* dst1 = dst0 + 8 * E_;
        #pragma unroll
        for (int nb = 0; nb < 12; nb++) {
            int d = nb * 8 + la * 2;
            dst0[d]     = O[nb][0] * inv0;
            dst0[d + 1] = O[nb][1] * inv0;
            dst1[d]     = O[nb][2] * inv1;
            dst1[d + 1] = O[nb][3] * inv1;
        }
    }
}

// ---------------------------------------------------------------------------
extern "C" void kernel_launch(void* const* d_in, const int* in_sizes, int n_in,
                              void* d_out, int out_size)
{
    const float* x  = (const float*)d_in[0];
    const float* Wq = (const float*)d_in[1];
    const float* bq = (const float*)d_in[2];
    const float* Wk = (const float*)d_in[3];
    const float* bk = (const float*)d_in[4];
    const float* Wo = (const float*)d_in[5];
    const float* bo = (const float*)d_in[6];
    float* out = (float*)d_out;

    cudaFuncSetAttribute(attn_kernel,
                         cudaFuncAttributeMaxDynamicSharedMemorySize,
                         ATTN_SMEM_BYTES);

    proj_kernel<<<dim3(32, 12, 2), 256>>>(x, Wq, bq, Wk, bk);
    attn_kernel<<<dim3(16, 16), 512, ATTN_SMEM_BYTES>>>();
    outproj_kernel<<<dim3(32, 12), 256>>>(Wo, bo, out);
}

// round 10
// speedup vs baseline: 1.2576x; 1.2576x over previous
#include <cuda_runtime.h>
#include <stdint.h>

#define B_ 2
#define S_ 2048
#define E_ 768
#define H_ 8
#define D_ 96
#define M_ 4096   // B*S

// scratch (no cudaMalloc allowed)
__device__ float g_Q[M_ * E_];   // [B,H,S,D]
__device__ float g_K[M_ * E_];   // [B,H,S,D] (also V — reference bug)
__device__ float g_AO[M_ * E_];  // attention output, [B,S,E]

// ---------------------------------------------------------------------------
// tf32 helpers
// ---------------------------------------------------------------------------
__device__ __forceinline__ uint32_t f2tf(float x) {
    uint32_t r;
    asm("cvt.rna.tf32.f32 %0, %1;" : "=r"(r) : "f"(x));
    return r;
}
__device__ __forceinline__ void split1(float x, uint32_t& h, uint32_t& l) {
    h = f2tf(x);
    l = f2tf(x - __uint_as_float(h));
}
__device__ __forceinline__ void mma4(float (&d)[4], uint4 a, uint2 b) {
    asm volatile(
        "mma.sync.aligned.m16n8k8.row.col.f32.tf32.tf32.f32 "
        "{%0,%1,%2,%3}, {%4,%5,%6,%7}, {%8,%9}, {%0,%1,%2,%3};"
        : "+f"(d[0]), "+f"(d[1]), "+f"(d[2]), "+f"(d[3])
        : "r"(a.x), "r"(a.y), "r"(a.z), "r"(a.w), "r"(b.x), "r"(b.y));
}

// Fragment-packed layouts:
//  A-pack (m16k8): word = ((rb*NKB + kb)*32 + lane)*4 + w
//  B-pack (n8k8):  word = ((nb*NKB + kb)*32 + lane)*2 + w

// ===========================================================================
// GEMM: C[128x64] = A[128x768] * W[768x64], TERMS-compensated tf32.
// (unchanged — R7-proven at 244us)
// ===========================================================================
template <int TERMS>
__device__ __forceinline__ void g_store_stage(
    uint32_t* AsH, uint32_t* AsL, uint32_t* BsH, uint32_t* BsL,
    int stage, const int (&ast)[2], const int (&bst)[2],
    const float (&a)[2][4], const float (&b)[2][2])
{
    uint32_t* pAH = AsH + stage * 2048;
    uint32_t* pAL = AsL + stage * 2048;
    uint32_t* pBH = BsH + stage * 1024;
    uint32_t* pBL = BsL + stage * 1024;
    #pragma unroll
    for (int g = 0; g < 2; g++) {
        uint32_t h[4], l[4];
        #pragma unroll
        for (int w = 0; w < 4; w++) split1(a[g][w], h[w], l[w]);
        *(uint4*)(pAH + ast[g]) = make_uint4(h[0], h[1], h[2], h[3]);
        if (TERMS >= 2)
            *(uint4*)(pAL + ast[g]) = make_uint4(l[0], l[1], l[2], l[3]);
        uint32_t bh[2], bl[2];
        #pragma unroll
        for (int w = 0; w < 2; w++) split1(b[g][w], bh[w], bl[w]);
        *(uint2*)(pBH + bst[g]) = make_uint2(bh[0], bh[1]);
        if (TERMS >= 3)
            *(uint2*)(pBL + bst[g]) = make_uint2(bl[0], bl[1]);
    }
}

template <int TERMS>
__device__ __forceinline__ void gemm_acc(
    const float* __restrict__ Ag, const float* __restrict__ Wg,
    int m0, int n0,
    uint32_t* AsH, uint32_t* AsL, uint32_t* BsH, uint32_t* BsL,
    float (&acc)[2][4][4])
{
    const int tid = threadIdx.x, lane = tid & 31, wid = tid >> 5;
    const int rbb = (wid >> 1) * 2;
    const int nbb = (wid & 1) * 4;

    int aof[2][4], ast[2], bof[2][2], bst[2];
    #pragma unroll
    for (int g = 0; g < 2; g++) {
        int gg = tid + g * 256;
        int blk = gg >> 6, kb = (gg >> 5) & 1, ln = gg & 31;
        int lq = ln >> 2, la = ln & 3;
        #pragma unroll
        for (int w = 0; w < 4; w++) {
            int r = blk * 16 + lq + 8 * (w & 1);
            int k = kb * 8 + la + 4 * (w >> 1);
            aof[g][w] = r * E_ + k;
        }
        ast[g] = gg * 4;
        #pragma unroll
        for (int w = 0; w < 2; w++) {
            int n = blk * 8 + lq;
            int k = kb * 8 + la + 4 * w;
            bof[g][w] = k * E_ + n;
        }
        bst[g] = gg * 2;
    }

    const float* Ap = Ag + (size_t)m0 * E_;
    const float* Wp = Wg + n0;

    float ar[2][2][4], br[2][2][2];
    #pragma unroll
    for (int g = 0; g < 2; g++) {
        #pragma unroll
        for (int w = 0; w < 4; w++) ar[0][g][w] = Ap[aof[g][w]];
        #pragma unroll
        for (int w = 0; w < 2; w++) br[0][g][w] = Wp[bof[g][w]];
    }
    g_store_stage<TERMS>(AsH, AsL, BsH, BsL, 0, ast, bst, ar[0], br[0]);
    #pragma unroll
    for (int g = 0; g < 2; g++) {
        #pragma unroll
        for (int w = 0; w < 4; w++) ar[1][g][w] = Ap[16 + aof[g][w]];
        #pragma unroll
        for (int w = 0; w < 2; w++) br[1][g][w] = Wp[16 * E_ + bof[g][w]];
    }
    __syncthreads();

    #pragma unroll 2
    for (int c = 0; c < 48; c++) {
        const int s = c & 1;
        if (c + 2 < 48) {
            const float* Ap2 = Ap + (c + 2) * 16;
            const float* Wp2 = Wp + (size_t)(c + 2) * 16 * E_;
            #pragma unroll
            for (int g = 0; g < 2; g++) {
                #pragma unroll
                for (int w = 0; w < 4; w++) ar[s][g][w] = Ap2[aof[g][w]];
                #pragma unroll
                for (int w = 0; w < 2; w++) br[s][g][w] = Wp2[bof[g][w]];
            }
        }
        if (c + 1 < 48)
            g_store_stage<TERMS>(AsH, AsL, BsH, BsL, s ^ 1, ast, bst,
                                 ar[s ^ 1], br[s ^ 1]);

        uint32_t* pAH = AsH + s * 2048;
        uint32_t* pAL = AsL + s * 2048;
        uint32_t* pBH = BsH + s * 1024;
        uint32_t* pBL = BsL + s * 1024;
        #pragma unroll
        for (int kb = 0; kb < 2; kb++) {
            uint4 ah0 = *(const uint4*)(pAH + rbb * 256 + kb * 128 + lane * 4);
            uint4 ah1 = *(const uint4*)(pAH + (rbb + 1) * 256 + kb * 128 + lane * 4);
            uint4 al0, al1;
            if (TERMS >= 2) {
                al0 = *(const uint4*)(pAL + rbb * 256 + kb * 128 + lane * 4);
                al1 = *(const uint4*)(pAL + (rbb + 1) * 256 + kb * 128 + lane * 4);
            }
            #pragma unroll
            for (int nf = 0; nf < 4; nf++) {
                uint2 bh = *(const uint2*)(pBH + (nbb + nf) * 128 + kb * 64 + lane * 2);
                mma4(acc[0][nf], ah0, bh);
                mma4(acc[1][nf], ah1, bh);
                if (TERMS >= 2) {
                    mma4(acc[0][nf], al0, bh);
                    mma4(acc[1][nf], al1, bh);
                }
                if (TERMS >= 3) {
                    uint2 bl = *(const uint2*)(pBL + (nbb + nf) * 128 + kb * 64 + lane * 2);
                    mma4(acc[0][nf], ah0, bl);
                    mma4(acc[1][nf], ah1, bl);
                }
            }
        }
        __syncthreads();
    }
}

__global__ void __launch_bounds__(256, 2) proj_kernel(
    const float* __restrict__ X,
    const float* __restrict__ Wq, const float* __restrict__ bq,
    const float* __restrict__ Wk, const float* __restrict__ bk)
{
    __shared__ uint32_t AsH[2 * 2048], AsL[2 * 2048];
    __shared__ uint32_t BsH[2 * 1024], BsL[2 * 1024];

    const float* W    = blockIdx.z ? Wk : Wq;
    const float* bias = blockIdx.z ? bk : bq;
    float* out        = blockIdx.z ? g_K : g_Q;

    const int m0 = blockIdx.x * 128, n0 = blockIdx.y * 64;
    const int lane = threadIdx.x & 31, wid = threadIdx.x >> 5;
    const int wm = (wid >> 1) * 32, wn = (wid & 1) * 32;
    const int la = lane & 3, lq = lane >> 2;

    float acc[2][4][4];
    #pragma unroll
    for (int i = 0; i < 2; i++)
        #pragma unroll
        for (int j = 0; j < 4; j++)
            #pragma unroll
            for (int k = 0; k < 4; k++) acc[i][j][k] = 0.f;

    gemm_acc<3>(X, W, m0, n0, AsH, AsL, BsH, BsL, acc);

    #pragma unroll
    for (int mi = 0; mi < 2; mi++) {
        int r = wm + mi * 16 + lq;
        #pragma unroll
        for (int nf = 0; nf < 4; nf++) {
            int n = n0 + wn + nf * 8 + la * 2;
            int h = n / D_, d = n % D_;
            int h1 = (n + 1) / D_, d1 = (n + 1) % D_;
            #pragma unroll
            for (int rr = 0; rr < 2; rr++) {
                int m = m0 + r + rr * 8;
                int bb = m >> 11, s = m & (S_ - 1);
                size_t base = ((size_t)(bb * H_)) * S_ * D_ + (size_t)s * D_;
                out[base + (size_t)h * S_ * D_ + d]   = acc[mi][nf][rr * 2 + 0] + bias[n];
                out[base + (size_t)h1 * S_ * D_ + d1] = acc[mi][nf][rr * 2 + 1] + bias[n + 1];
            }
        }
    }
}

__global__ void __launch_bounds__(256, 2) outproj_kernel(
    const float* __restrict__ Wo, const float* __restrict__ bo,
    float* __restrict__ Y)
{
    __shared__ uint32_t AsH[2 * 2048], AsL[2 * 2048];
    __shared__ uint32_t BsH[2 * 1024], BsL[2 * 1024];

    const int m0 = blockIdx.x * 128, n0 = blockIdx.y * 64;
    const int lane = threadIdx.x & 31, wid = threadIdx.x >> 5;
    const int wm = (wid >> 1) * 32, wn = (wid & 1) * 32;
    const int la = lane & 3, lq = lane >> 2;

    float acc[2][4][4];
    #pragma unroll
    for (int i = 0; i < 2; i++)
        #pragma unroll
        for (int j = 0; j < 4; j++)
            #pragma unroll
            for (int k = 0; k < 4; k++) acc[i][j][k] = 0.f;

    gemm_acc<2>(g_AO, Wo, m0, n0, AsH, AsL, BsH, BsL, acc);

    #pragma unroll
    for (int mi = 0; mi < 2; mi++) {
        int r = wm + mi * 16 + lq;
        #pragma unroll
        for (int nf = 0; nf < 4; nf++) {
            int n = n0 + wn + nf * 8 + la * 2;
            #pragma unroll
            for (int rr = 0; rr < 2; rr++) {
                int m = m0 + r + rr * 8;
                Y[(size_t)m * E_ + n]     = acc[mi][nf][rr * 2 + 0] + bo[n];
                Y[(size_t)m * E_ + n + 1] = acc[mi][nf][rr * 2 + 1] + bo[n + 1];
            }
        }
    }
}

// ===========================================================================
// Flash attention, mma.sync tf32, V == K (reference bug), no-max softmax.
// R7 structure (16 compute warps; rg=wid&7 rows, cg=wid>>3 key-half) with
// register-resident P (D->A fragment shuffle, proven in R8):
//   QK^T 3xTF32 over warp's 16 rows x 32 keys
//   exp -> tf32 P kept in registers, shuffled to A-frag layout
//   PV 1xTF32: warp's 32 keys x ALL 96 d-cols -> partial O[12][4]
//   final: cg=1 partial O merged into cg=0 via smem (stride 97), once.
// 2 syncthreads per tile, no P smem traffic.
// Smem (words): Q-pack hi/lo 2x12288 | K-pack hi/lo 6144+6144 | V^T 6144 | Ls
// O-merge buffer (128x97) aliases the Q region after the loop.
// ===========================================================================
#define AQ_H 0
#define AQ_L 12288
#define AK_H 24576
#define AK_L 30720
#define AV_  36864
#define AL_  43008
#define ATTN_WORDS (AL_ + 256)
#define ATTN_SMEM_BYTES (ATTN_WORDS * 4)   // 173,056

__global__ void __launch_bounds__(512, 1) attn_kernel()
{
    extern __shared__ uint32_t sm[];
    uint32_t* KsH = sm + AK_H;
    uint32_t* KsL = sm + AK_L;
    uint32_t* Vs  = sm + AV_;
    float*    Ls  = (float*)(sm + AL_);

    const int tid = threadIdx.x, lane = tid & 31, wid = tid >> 5;
    const int la = lane & 3, lq = lane >> 2;
    const int rg = wid & 7, cg = wid >> 3;
    const int bh = blockIdx.y, qt = blockIdx.x;

    const float* Qg = g_Q + (size_t)bh * S_ * D_ + (size_t)qt * 128 * D_;
    const float* Kg = g_K + (size_t)bh * S_ * D_;

    // ---- pack Q tile (128x96) into hi/lo A-pack ----
    #pragma unroll
    for (int i = 0; i < 6; i++) {
        int gg = tid + i * 512;               // < 3072 groups
        int rb = gg / 384, rem = gg - rb * 384;
        int kb = rem >> 5, ln = rem & 31;
        int glq = ln >> 2, gla = ln & 3;
        float v[4];
        #pragma unroll
        for (int w = 0; w < 4; w++) {
            int r = rb * 16 + glq + 8 * (w & 1);
            int k = kb * 8 + gla + 4 * (w >> 1);
            v[w] = Qg[r * D_ + k];
        }
        uint32_t h[4], l[4];
        #pragma unroll
        for (int w = 0; w < 4; w++) split1(v[w], h[w], l[w]);
        *(uint4*)(sm + AQ_H + gg * 4) = make_uint4(h[0], h[1], h[2], h[3]);
        *(uint4*)(sm + AQ_L + gg * 4) = make_uint4(l[0], l[1], l[2], l[3]);
    }

    // K-tile pack mapping (all 16 warps): warp -> (key-block knb, d-half kbh)
    const int knb = wid & 7;
    const int kbh = (wid >> 3) * 6;
    const float* Kp = Kg + (size_t)(knb * 8 + lq) * D_ + la;

    const int r0 = rg * 16 + lq;

    float O[12][4];
    #pragma unroll
    for (int nb = 0; nb < 12; nb++)
        #pragma unroll
        for (int r = 0; r < 4; r++) O[nb][r] = 0.f;
    float ls0 = 0.f, ls1 = 0.f;

    // prefetch K tile 0
    float kpf[6][2];
    #pragma unroll
    for (int j = 0; j < 6; j++) {
        kpf[j][0] = Kp[(kbh + j) * 8];
        kpf[j][1] = Kp[(kbh + j) * 8 + 4];
    }

    // D->A shuffle lane constants
    const int s0l = (lq << 2) + (la >> 1);
    const int s1l = s0l + 2;
    const bool odd = la & 1;

    for (int kt = 0; kt < 32; kt++) {
        __syncthreads();                       // prev Ks/Vs consumed
        // pack K tile: hi/lo B-pack + V^T hi B-pack
        #pragma unroll
        for (int j = 0; j < 6; j++) {
            int kbd = kbh + j;
            uint32_t h0, l0, h1, l1;
            split1(kpf[j][0], h0, l0);
            split1(kpf[j][1], h1, l1);
            *(uint2*)(KsH + (knb * 12 + kbd) * 64 + lane * 2) = make_uint2(h0, h1);
            *(uint2*)(KsL + (knb * 12 + kbd) * 64 + lane * 2) = make_uint2(l0, l1);
            int vbase = (kbd * 8 + knb) * 64 + (lq >> 2);
            Vs[vbase + (la * 4 + (lq & 3)) * 2]       = h0;
            Vs[vbase + ((la + 4) * 4 + (lq & 3)) * 2] = h1;
        }
        __syncthreads();

        if (kt < 31) {                         // prefetch next K tile
            const float* Kp2 = Kp + (size_t)(kt + 1) * 64 * D_;
            #pragma unroll
            for (int j = 0; j < 6; j++) {
                kpf[j][0] = Kp2[(kbh + j) * 8];
                kpf[j][1] = Kp2[(kbh + j) * 8 + 4];
            }
        }

        // S = Q K^T : rows [rg*16,+16) x cols [cg*32,+32), 3xTF32
        float s4[4][4];
        #pragma unroll
        for (int nf = 0; nf < 4; nf++)
            #pragma unroll
            for (int k = 0; k < 4; k++) s4[nf][k] = 0.f;

        #pragma unroll
        for (int kb = 0; kb < 12; kb++) {
            uint4 ah = *(const uint4*)(sm + AQ_H + (rg * 12 + kb) * 128 + lane * 4);
            uint4 al = *(const uint4*)(sm + AQ_L + (rg * 12 + kb) * 128 + lane * 4);
            #pragma unroll
            for (int nf = 0; nf < 4; nf++) {
                int nb = cg * 4 + nf;
                uint2 bhv = *(const uint2*)(KsH + (nb * 12 + kb) * 64 + lane * 2);
                uint2 blv = *(const uint2*)(KsL + (nb * 12 + kb) * 64 + lane * 2);
                mma4(s4[nf], ah, bhv);
                mma4(s4[nf], al, bhv);
                mma4(s4[nf], ah, blv);
            }
        }

        // per 8-key block: exp -> tf32 P (regs) -> A-frag shuffle -> PV
        #pragma unroll
        for (int nf = 0; nf < 4; nf++) {
            float p0 = __expf(s4[nf][0]);
            float p1 = __expf(s4[nf][1]);
            float p2 = __expf(s4[nf][2]);
            float p3 = __expf(s4[nf][3]);
            ls0 += p0 + p1;
            ls1 += p2 + p3;
            uint32_t q0 = f2tf(p0), q1 = f2tf(p1), q2 = f2tf(p2), q3 = f2tf(p3);
            uint32_t t0 = __shfl_sync(0xffffffffu, q0, s0l);
            uint32_t t1 = __shfl_sync(0xffffffffu, q1, s0l);
            uint32_t t2 = __shfl_sync(0xffffffffu, q2, s0l);
            uint32_t t3 = __shfl_sync(0xffffffffu, q3, s0l);
            uint32_t u0 = __shfl_sync(0xffffffffu, q0, s1l);
            uint32_t u1 = __shfl_sync(0xffffffffu, q1, s1l);
            uint32_t u2 = __shfl_sync(0xffffffffu, q2, s1l);
            uint32_t u3 = __shfl_sync(0xffffffffu, q3, s1l);
            uint4 a = make_uint4(odd ? t1 : t0, odd ? t3 : t2,
                                 odd ? u1 : u0, odd ? u3 : u2);
            const int kb = cg * 4 + nf;        // warp's key block in 0..7
            #pragma unroll
            for (int nb = 0; nb < 12; nb++) {
                uint2 bv = *(const uint2*)(Vs + (nb * 8 + kb) * 64 + lane * 2);
                mma4(O[nb], a, bv);
            }
        }
    }

    // row sums: quad-lane reduce (covers warp's 32 keys), then merge cg halves
    ls0 += __shfl_xor_sync(0xffffffffu, ls0, 1);
    ls0 += __shfl_xor_sync(0xffffffffu, ls0, 2);
    ls1 += __shfl_xor_sync(0xffffffffu, ls1, 1);
    ls1 += __shfl_xor_sync(0xffffffffu, ls1, 2);
    if (la == 0) {
        Ls[r0 * 2 + cg]       = ls0;
        Ls[(r0 + 8) * 2 + cg] = ls1;
    }
    __syncthreads();                           // Ls complete; Q region dead

    // merge partial O: cg=1 -> smem (stride 97), cg=0 adds + stores
    float* Om = (float*)sm;                    // 128 x 97 floats (< Q region)
    if (cg == 1) {
        #pragma unroll
        for (int nb = 0; nb < 12; nb++) {
            int d = nb * 8 + la * 2;
            Om[r0 * 97 + d]           = O[nb][0];
            Om[r0 * 97 + d + 1]       = O[nb][1];
            Om[(r0 + 8) * 97 + d]     = O[nb][2];
            Om[(r0 + 8) * 97 + d + 1] = O[nb][3];
        }
    }
    __syncthreads();

    if (cg == 0) {
        const float SCALE = 0.10206207261596577f;   // 96^-0.5
        float inv0 = SCALE / (Ls[r0 * 2] + Ls[r0 * 2 + 1]);
        float inv1 = SCALE / (Ls[(r0 + 8) * 2] + Ls[(r0 + 8) * 2 + 1]);
        const int bb = bh >> 3, h = bh & 7;
        int srow0 = qt * 128 + r0;
        float* dst0 = g_AO + ((size_t)(bb * S_ + srow0)) * E_ + h * D_;
        float* dst1 = dst0 + 8 * E_;
        #pragma unroll
        for (int nb = 0; nb < 12; nb++) {
            int d = nb * 8 + la * 2;
            dst0[d]     = (O[nb][0] + Om[r0 * 97 + d])           * inv0;
            dst0[d + 1] = (O[nb][1] + Om[r0 * 97 + d + 1])       * inv0;
            dst1[d]     = (O[nb][2] + Om[(r0 + 8) * 97 + d])     * inv1;
            dst1[d + 1] = (O[nb][3] + Om[(r0 + 8) * 97 + d + 1]) * inv1;
        }
    }
}

// ---------------------------------------------------------------------------
extern "C" void kernel_launch(void* const* d_in, const int* in_sizes, int n_in,
                              void* d_out, int out_size)
{
    const float* x  = (const float*)d_in[0];
    const float* Wq = (const float*)d_in[1];
    const float* bq = (const float*)d_in[2];
    const float* Wk = (const float*)d_in[3];
    const float* bk = (const float*)d_in[4];
    const float* Wo = (const float*)d_in[5];
    const float* bo = (const float*)d_in[6];
    float* out = (float*)d_out;

    cudaFuncSetAttribute(attn_kernel,
                         cudaFuncAttributeMaxDynamicSharedMemorySize,
                         ATTN_SMEM_BYTES);

    proj_kernel<<<dim3(32, 12, 2), 256>>>(x, Wq, bq, Wk, bk);
    attn_kernel<<<dim3(16, 16), 512, ATTN_SMEM_BYTES>>>();
    outproj_kernel<<<dim3(32, 12), 256>>>(Wo, bo, out);
}

// round 12
// speedup vs baseline: 1.6646x; 1.3237x over previous
#include <cuda_runtime.h>
#include <cuda_bf16.h>
#include <stdint.h>

#define B_ 2
#define S_ 2048
#define E_ 768
#define H_ 8
#define D_ 96
#define M_ 4096   // B*S

// scratch (no cudaMalloc allowed)
__device__ float g_Q[M_ * E_];   // [B,H,S,D]
__device__ float g_K[M_ * E_];   // [B,H,S,D] (also V — reference bug)
__device__ float g_AO[M_ * E_];  // attention output, [B,S,E]

// ---------------------------------------------------------------------------
// bf16 helpers: x = b0 + b1 (hi + residual), packed 2-per-uint32
// ---------------------------------------------------------------------------
__device__ __forceinline__ void splitb2(float x, float y,
                                        uint32_t& h, uint32_t& l) {
    __nv_bfloat16 hx = __float2bfloat16_rn(x);
    __nv_bfloat16 hy = __float2bfloat16_rn(y);
    __nv_bfloat162 hv = __halves2bfloat162(hx, hy);
    h = *(uint32_t*)&hv;
    __nv_bfloat162 lv = __halves2bfloat162(
        __float2bfloat16_rn(x - __bfloat162float(hx)),
        __float2bfloat16_rn(y - __bfloat162float(hy)));
    l = *(uint32_t*)&lv;
}

__device__ __forceinline__ void mmab(float (&d)[4], uint4 a, uint2 b) {
    asm volatile(
        "mma.sync.aligned.m16n8k16.row.col.f32.bf16.bf16.f32 "
        "{%0,%1,%2,%3}, {%4,%5,%6,%7}, {%8,%9}, {%0,%1,%2,%3};"
        : "+f"(d[0]), "+f"(d[1]), "+f"(d[2]), "+f"(d[3])
        : "r"(a.x), "r"(a.y), "r"(a.z), "r"(a.w), "r"(b.x), "r"(b.y));
}

// Fragment-packed layouts (m16n8k16 bf16):
//  A-pack: group (rb, kb16); per lane uint4:
//    w0=(lq, 2la..+1) w1=(lq+8, 2la..+1) w2=(lq, 2la+8..+9) w3=(lq+8, 2la+8..+9)
//  B-pack: group (nb, kb16); per lane uint2:
//    w0=(n=lq, k=2la..+1)  w1=(n=lq, k=2la+8..+9)

// ===========================================================================
// GEMM: C[128x64] = A[128x768] * W[768x64], bf16x3 (a0b0+a1b0+a0b1).
// 256 threads, 8 warps (4m x 2n of 32x32). BK=16, double-buffered stages.
// Stage words: AH 1024 | AL 1024 | BH 512 | BL 512  (stride 3072)
// ===========================================================================
__device__ __forceinline__ void g_loadA(const float* P, float* d) {
    float2 v0 = *(const float2*)P;
    float2 v1 = *(const float2*)(P + 8 * E_);
    float2 v2 = *(const float2*)(P + 8);
    float2 v3 = *(const float2*)(P + 8 * E_ + 8);
    d[0] = v0.x; d[1] = v0.y; d[2] = v1.x; d[3] = v1.y;
    d[4] = v2.x; d[5] = v2.y; d[6] = v3.x; d[7] = v3.y;
}
__device__ __forceinline__ void g_loadB(const float* P, float* d) {
    d[0] = P[0];
    d[1] = P[E_];
    d[2] = P[8 * E_];
    d[3] = P[9 * E_];
}
__device__ __forceinline__ void g_store(uint32_t* sg, int s, int ast, int bst,
                                        const float* a, const float* b) {
    uint32_t* base = sg + s * 3072;
    uint32_t h[4], l[4];
    splitb2(a[0], a[1], h[0], l[0]);
    splitb2(a[2], a[3], h[1], l[1]);
    splitb2(a[4], a[5], h[2], l[2]);
    splitb2(a[6], a[7], h[3], l[3]);
    *(uint4*)(base + ast)        = make_uint4(h[0], h[1], h[2], h[3]);
    *(uint4*)(base + 1024 + ast) = make_uint4(l[0], l[1], l[2], l[3]);
    uint32_t bh0, bl0, bh1, bl1;
    splitb2(b[0], b[1], bh0, bl0);
    splitb2(b[2], b[3], bh1, bl1);
    *(uint2*)(base + 2048 + bst) = make_uint2(bh0, bh1);
    *(uint2*)(base + 2560 + bst) = make_uint2(bl0, bl1);
}

__device__ __forceinline__ void gemm_bf(
    const float* __restrict__ Ag, const float* __restrict__ Wg,
    int m0, int n0, uint32_t* sg, float (&acc)[2][4][4])
{
    const int tid = threadIdx.x, lane = tid & 31, wid = tid >> 5;
    const int rbb = (wid >> 1) * 2, nbb = (wid & 1) * 4;

    const float* Ap = Ag + (size_t)(m0 + (tid >> 5) * 16 + ((lane >> 2))) * E_ + (lane & 3) * 2;
    const float* Wp = Wg + (size_t)((lane & 3) * 2) * E_ + n0 + (tid >> 5) * 8 + (lane >> 2);
    const int ast = tid * 4, bst = tid * 2;

    float ar[2][8], br[2][4];
    g_loadA(Ap, ar[0]);
    g_loadB(Wp, br[0]);
    g_store(sg, 0, ast, bst, ar[0], br[0]);
    g_loadA(Ap + 16, ar[1]);
    g_loadB(Wp + 16 * E_, br[1]);
    __syncthreads();

    #pragma unroll 2
    for (int c = 0; c < 48; c++) {
        const int s = c & 1;
        if (c + 2 < 48) {
            g_loadA(Ap + (c + 2) * 16, ar[s]);
            g_loadB(Wp + (size_t)(c + 2) * 16 * E_, br[s]);
        }
        if (c + 1 < 48)
            g_store(sg, s ^ 1, ast, bst, ar[s ^ 1], br[s ^ 1]);

        uint32_t* AH = sg + s * 3072;
        uint32_t* ALp = AH + 1024;
        uint32_t* BH = AH + 2048;
        uint32_t* BL = AH + 2560;
        uint4 ah0 = *(const uint4*)(AH + (rbb * 32 + lane) * 4);
        uint4 ah1 = *(const uint4*)(AH + ((rbb + 1) * 32 + lane) * 4);
        uint4 al0 = *(const uint4*)(ALp + (rbb * 32 + lane) * 4);
        uint4 al1 = *(const uint4*)(ALp + ((rbb + 1) * 32 + lane) * 4);
        #pragma unroll
        for (int nf = 0; nf < 4; nf++) {
            uint2 bh = *(const uint2*)(BH + ((nbb + nf) * 32 + lane) * 2);
            uint2 bl = *(const uint2*)(BL + ((nbb + nf) * 32 + lane) * 2);
            mmab(acc[0][nf], ah0, bh);
            mmab(acc[0][nf], al0, bh);
            mmab(acc[0][nf], ah0, bl);
            mmab(acc[1][nf], ah1, bh);
            mmab(acc[1][nf], al1, bh);
            mmab(acc[1][nf], ah1, bl);
        }
        __syncthreads();
    }
}

// Projection: out = x@W+b scattered to [B,H,S,D]; z=0 -> Q, z=1 -> K.
__global__ void __launch_bounds__(256, 2) proj_kernel(
    const float* __restrict__ X,
    const float* __restrict__ Wq, const float* __restrict__ bq,
    const float* __restrict__ Wk, const float* __restrict__ bk)
{
    __shared__ uint32_t sg[2 * 3072];

    const float* W    = blockIdx.z ? Wk : Wq;
    const float* bias = blockIdx.z ? bk : bq;
    float* out        = blockIdx.z ? g_K : g_Q;

    const int m0 = blockIdx.x * 128, n0 = blockIdx.y * 64;
    const int lane = threadIdx.x & 31, wid = threadIdx.x >> 5;
    const int wm = (wid >> 1) * 32, wn = (wid & 1) * 32;
    const int la = lane & 3, lq = lane >> 2;

    float acc[2][4][4];
    #pragma unroll
    for (int i = 0; i < 2; i++)
        #pragma unroll
        for (int j = 0; j < 4; j++)
            #pragma unroll
            for (int k = 0; k < 4; k++) acc[i][j][k] = 0.f;

    gemm_bf(X, W, m0, n0, sg, acc);

    #pragma unroll
    for (int mi = 0; mi < 2; mi++) {
        int r = wm + mi * 16 + lq;
        #pragma unroll
        for (int nf = 0; nf < 4; nf++) {
            int n = n0 + wn + nf * 8 + la * 2;
            int h = n / D_, d = n % D_;
            int h1 = (n + 1) / D_, d1 = (n + 1) % D_;
            #pragma unroll
            for (int rr = 0; rr < 2; rr++) {
                int m = m0 + r + rr * 8;
                int bb = m >> 11, s = m & (S_ - 1);
                size_t base = ((size_t)(bb * H_)) * S_ * D_ + (size_t)s * D_;
                out[base + (size_t)h * S_ * D_ + d]   = acc[mi][nf][rr * 2 + 0] + bias[n];
                out[base + (size_t)h1 * S_ * D_ + d1] = acc[mi][nf][rr * 2 + 1] + bias[n + 1];
            }
        }
    }
}

// Output projection: Y = g_AO @ Wo + bo.
__global__ void __launch_bounds__(256, 2) outproj_kernel(
    const float* __restrict__ Wo, const float* __restrict__ bo,
    float* __restrict__ Y)
{
    __shared__ uint32_t sg[2 * 3072];

    const int m0 = blockIdx.x * 128, n0 = blockIdx.y * 64;
    const int lane = threadIdx.x & 31, wid = threadIdx.x >> 5;
    const int wm = (wid >> 1) * 32, wn = (wid & 1) * 32;
    const int la = lane & 3, lq = lane >> 2;

    float acc[2][4][4];
    #pragma unroll
    for (int i = 0; i < 2; i++)
        #pragma unroll
        for (int j = 0; j < 4; j++)
            #pragma unroll
            for (int k = 0; k < 4; k++) acc[i][j][k] = 0.f;

    gemm_bf(g_AO, Wo, m0, n0, sg, acc);

    #pragma unroll
    for (int mi = 0; mi < 2; mi++) {
        int r = wm + mi * 16 + lq;
        #pragma unroll
        for (int nf = 0; nf < 4; nf++) {
            int n = n0 + wn + nf * 8 + la * 2;
            #pragma unroll
            for (int rr = 0; rr < 2; rr++) {
                int m = m0 + r + rr * 8;
                Y[(size_t)m * E_ + n]     = acc[mi][nf][rr * 2 + 0] + bo[n];
                Y[(size_t)m * E_ + n + 1] = acc[mi][nf][rr * 2 + 1] + bo[n + 1];
            }
        }
    }
}

// ===========================================================================
// Flash attention, bf16x3 mma (k16), V == K (reference bug), no-max softmax.
// 16 compute warps: rg=wid&7 (16 rows), cg=wid>>3 (32-key half).
// QK^T: 3-mma bf16 (Qh/Ql x Kh/Kl). exp(S) packs DIRECTLY into PV A-frags
// (k16 col pairing == D-frag pairing; no shuffles). PV: 3-mma bf16, warp's
// 32 keys x all 96 d -> partial O; cg halves merged once via smem.
// Smem words: QsH/QsL 6144 ea | KsH/KsL 3072 ea | VsH/VsL 3072 ea | Ls 256
// ===========================================================================
#define AQ_H 0
#define AQ_L 6144
#define AK_H 12288
#define AK_L 15360
#define AV_H 18432
#define AV_L 21504
#define AL_  24576
#define ATTN_WORDS (AL_ + 256)
#define ATTN_SMEM_BYTES (ATTN_WORDS * 4)   // 99,328

__global__ void __launch_bounds__(512, 1) attn_kernel()
{
    extern __shared__ uint32_t sm[];
    float* Ls = (float*)(sm + AL_);

    const int tid = threadIdx.x, lane = tid & 31, wid = tid >> 5;
    const int la = lane & 3, lq = lane >> 2;
    const int rg = wid & 7, cg = wid >> 3;
    const int bh = blockIdx.y, qt = blockIdx.x;

    const float* Qg = g_Q + (size_t)bh * S_ * D_ + (size_t)qt * 128 * D_;
    const float* Kg = g_K + (size_t)bh * S_ * D_;

    // ---- pack Q tile (128x96) into hi/lo A-pack (8 rb x 6 kb16) ----
    #pragma unroll
    for (int i = 0; i < 3; i++) {
        int gg = tid + i * 512;               // < 1536
        int grp = gg >> 5, ln = gg & 31;
        int rb = grp / 6, kb = grp - rb * 6;
        int glq = ln >> 2, gla = ln & 3;
        int r = rb * 16 + glq, c = kb * 16 + gla * 2;
        float2 v0 = *(const float2*)(Qg + r * D_ + c);
        float2 v1 = *(const float2*)(Qg + (r + 8) * D_ + c);
        float2 v2 = *(const float2*)(Qg + r * D_ + c + 8);
        float2 v3 = *(const float2*)(Qg + (r + 8) * D_ + c + 8);
        uint32_t h[4], l[4];
        splitb2(v0.x, v0.y, h[0], l[0]);
        splitb2(v1.x, v1.y, h[1], l[1]);
        splitb2(v2.x, v2.y, h[2], l[2]);
        splitb2(v3.x, v3.y, h[3], l[3]);
        *(uint4*)(sm + AQ_H + gg * 4) = make_uint4(h[0], h[1], h[2], h[3]);
        *(uint4*)(sm + AQ_L + gg * 4) = make_uint4(l[0], l[1], l[2], l[3]);
    }

    // K/V pack assignments: warp handles groups wid*3 .. wid*3+2 of 48
    int koff[3], voff[3];
    #pragma unroll
    for (int j = 0; j < 3; j++) {
        int g = wid * 3 + j;
        int knb = g / 6, kkb = g - knb * 6;        // K: 8 nb x 6 kb16
        koff[j] = (knb * 8 + lq) * D_ + kkb * 16 + la * 2;
        int vnb = g >> 2, vkb = g & 3;             // V^T: 12 nb x 4 kb16
        voff[j] = (vkb * 16 + la * 2) * D_ + vnb * 8 + lq;
    }

    float O[12][4];
    #pragma unroll
    for (int nb = 0; nb < 12; nb++)
        #pragma unroll
        for (int r = 0; r < 4; r++) O[nb][r] = 0.f;
    float ls0 = 0.f, ls1 = 0.f;

    // prefetch tile 0
    float kpr[3][4], vpr[3][4];
    #pragma unroll
    for (int j = 0; j < 3; j++) {
        float2 f0 = *(const float2*)(Kg + koff[j]);
        float2 f1 = *(const float2*)(Kg + koff[j] + 8);
        kpr[j][0] = f0.x; kpr[j][1] = f0.y; kpr[j][2] = f1.x; kpr[j][3] = f1.y;
        vpr[j][0] = Kg[voff[j]];
        vpr[j][1] = Kg[voff[j] + D_];
        vpr[j][2] = Kg[voff[j] + 8 * D_];
        vpr[j][3] = Kg[voff[j] + 9 * D_];
    }

    for (int kt = 0; kt < 32; kt++) {
        __syncthreads();                       // prev K/V consumed
        // publish K-pack + V^T-pack (hi/lo) from prefetch regs
        #pragma unroll
        for (int j = 0; j < 3; j++) {
            int g = wid * 3 + j;
            uint32_t h0, l0, h1, l1;
            splitb2(kpr[j][0], kpr[j][1], h0, l0);
            splitb2(kpr[j][2], kpr[j][3], h1, l1);
            *(uint2*)(sm + AK_H + (g * 32 + lane) * 2) = make_uint2(h0, h1);
            *(uint2*)(sm + AK_L + (g * 32 + lane) * 2) = make_uint2(l0, l1);
            splitb2(vpr[j][0], vpr[j][1], h0, l0);
            splitb2(vpr[j][2], vpr[j][3], h1, l1);
            *(uint2*)(sm + AV_H + (g * 32 + lane) * 2) = make_uint2(h0, h1);
            *(uint2*)(sm + AV_L + (g * 32 + lane) * 2) = make_uint2(l0, l1);
        }
        __syncthreads();

        if (kt < 31) {                         // prefetch next tile
            const float* Kn = Kg + (size_t)(kt + 1) * 64 * D_;
            #pragma unroll
            for (int j = 0; j < 3; j++) {
                float2 f0 = *(const float2*)(Kn + koff[j]);
                float2 f1 = *(const float2*)(Kn + koff[j] + 8);
                kpr[j][0] = f0.x; kpr[j][1] = f0.y;
                kpr[j][2] = f1.x; kpr[j][3] = f1.y;
                vpr[j][0] = Kn[voff[j]];
                vpr[j][1] = Kn[voff[j] + D_];
                vpr[j][2] = Kn[voff[j] + 8 * D_];
                vpr[j][3] = Kn[voff[j] + 9 * D_];
            }
        }

        // S = Q K^T : rows [rg*16,+16) x keys [cg*32,+32), bf16x3
        float s4[4][4];
        #pragma unroll
        for (int nf = 0; nf < 4; nf++)
            #pragma unroll
            for (int k = 0; k < 4; k++) s4[nf][k] = 0.f;

        #pragma unroll
        for (int kb = 0; kb < 6; kb++) {
            uint4 ah = *(const uint4*)(sm + AQ_H + ((rg * 6 + kb) * 32 + lane) * 4);
            uint4 al = *(const uint4*)(sm + AQ_L + ((rg * 6 + kb) * 32 + lane) * 4);
            #pragma unroll
            for (int nf = 0; nf < 4; nf++) {
                int nb = cg * 4 + nf;
                uint2 bhv = *(const uint2*)(sm + AK_H + ((nb * 6 + kb) * 32 + lane) * 2);
                uint2 blv = *(const uint2*)(sm + AK_L + ((nb * 6 + kb) * 32 + lane) * 2);
                mmab(s4[nf], ah, bhv);
                mmab(s4[nf], al, bhv);
                mmab(s4[nf], ah, blv);
            }
        }

        // exp (no max) -> bf16 hi/lo P packed directly into PV A-frags
        uint32_t aH[2][4], aLr[2][4];
        #pragma unroll
        for (int nf = 0; nf < 4; nf++) {
            float p0 = __expf(s4[nf][0]);
            float p1 = __expf(s4[nf][1]);
            float p2 = __expf(s4[nf][2]);
            float p3 = __expf(s4[nf][3]);
            ls0 += p0 + p1;
            ls1 += p2 + p3;
            uint32_t h01, l01, h23, l23;
            splitb2(p0, p1, h01, l01);
            splitb2(p2, p3, h23, l23);
            int kbl = nf >> 1, o = (nf & 1) * 2;
            aH[kbl][o]      = h01;
            aH[kbl][o + 1]  = h23;
            aLr[kbl][o]     = l01;
            aLr[kbl][o + 1] = l23;
        }

        // O += P @ V (V == K): warp's 2 kb16 x all 12 d-blocks, bf16x3
        #pragma unroll
        for (int kbl = 0; kbl < 2; kbl++) {
            uint4 pa = make_uint4(aH[kbl][0], aH[kbl][1], aH[kbl][2], aH[kbl][3]);
            uint4 pl = make_uint4(aLr[kbl][0], aLr[kbl][1], aLr[kbl][2], aLr[kbl][3]);
            int kb16 = cg * 2 + kbl;
            #pragma unroll
            for (int nb = 0; nb < 12; nb++) {
                uint2 vh = *(const uint2*)(sm + AV_H + ((nb * 4 + kb16) * 32 + lane) * 2);
                uint2 vl = *(const uint2*)(sm + AV_L + ((nb * 4 + kb16) * 32 + lane) * 2);
                mmab(O[nb], pa, vh);
                mmab(O[nb], pa, vl);
                mmab(O[nb], pl, vh);
            }
        }
    }

    // row sums: quad-lane reduce, then merge cg halves
    ls0 += __shfl_xor_sync(0xffffffffu, ls0, 1);
    ls0 += __shfl_xor_sync(0xffffffffu, ls0, 2);
    ls1 += __shfl_xor_sync(0xffffffffu, ls1, 1);
    ls1 += __shfl_xor_sync(0xffffffffu, ls1, 2);
    const int r0 = rg * 16 + lq;
    if (la == 0) {
        Ls[r0 * 2 + cg]       = ls0;
        Ls[(r0 + 8) * 2 + cg] = ls1;
    }
    __syncthreads();                           // Ls done; Q/K regions dead

    // merge partial O: cg=1 -> smem (stride 97), cg=0 adds + stores
    float* Om = (float*)sm;                    // 128 x 97 floats
    if (cg == 1) {
        #pragma unroll
        for (int nb = 0; nb < 12; nb++) {
            int d = nb * 8 + la * 2;
            Om[r0 * 97 + d]           = O[nb][0];
            Om[r0 * 97 + d + 1]       = O[nb][1];
            Om[(r0 + 8) * 97 + d]     = O[nb][2];
            Om[(r0 + 8) * 97 + d + 1] = O[nb][3];
        }
    }
    __syncthreads();

    if (cg == 0) {
        const float SCALE = 0.10206207261596577f;   // 96^-0.5
        float inv0 = SCALE / (Ls[r0 * 2] + Ls[r0 * 2 + 1]);
        float inv1 = SCALE / (Ls[(r0 + 8) * 2] + Ls[(r0 + 8) * 2 + 1]);
        const int bb = bh >> 3, h = bh & 7;
        int srow0 = qt * 128 + r0;
        float* dst0 = g_AO + ((size_t)(bb * S_ + srow0)) * E_ + h * D_;
        float* dst1 = dst0 + 8 * E_;
        #pragma unroll
        for (int nb = 0; nb < 12; nb++) {
            int d = nb * 8 + la * 2;
            dst0[d]     = (O[nb][0] + Om[r0 * 97 + d])           * inv0;
            dst0[d + 1] = (O[nb][1] + Om[r0 * 97 + d + 1])       * inv0;
            dst1[d]     = (O[nb][2] + Om[(r0 + 8) * 97 + d])     * inv1;
            dst1[d + 1] = (O[nb][3] + Om[(r0 + 8) * 97 + d + 1]) * inv1;
        }
    }
}

// ---------------------------------------------------------------------------
extern "C" void kernel_launch(void* const* d_in, const int* in_sizes, int n_in,
                              void* d_out, int out_size)
{
    const float* x  = (const float*)d_in[0];
    const float* Wq = (const float*)d_in[1];
    const float* bq = (const float*)d_in[2];
    const float* Wk = (const float*)d_in[3];
    const float* bk = (const float*)d_in[4];
    const float* Wo = (const float*)d_in[5];
    const float* bo = (const float*)d_in[6];
    float* out = (float*)d_out;

    cudaFuncSetAttribute(attn_kernel,
                         cudaFuncAttributeMaxDynamicSharedMemorySize,
                         ATTN_SMEM_BYTES);

    proj_kernel<<<dim3(32, 12, 2), 256>>>(x, Wq, bq, Wk, bk);
    attn_kernel<<<dim3(16, 16), 512, ATTN_SMEM_BYTES>>>();
    outproj_kernel<<<dim3(32, 12), 256>>>(Wo, bo, out);
}

// round 15
// speedup vs baseline: 1.7627x; 1.0590x over previous
#include <cuda_runtime.h>
#include <cuda_bf16.h>
#include <stdint.h>

#define B_ 2
#define S_ 2048
#define E_ 768
#define H_ 8
#define D_ 96
#define M_ 4096   // B*S

// scratch (no cudaMalloc allowed)
__device__ float g_Q[M_ * E_];   // [B,H,S,D]
__device__ float g_K[M_ * E_];   // [B,H,S,D] (also V — reference bug)
__device__ float g_AO[M_ * E_];  // attention output, [B,S,E]

// ---------------------------------------------------------------------------
// bf16 / tf32 helpers
// ---------------------------------------------------------------------------
__device__ __forceinline__ void splitb2(float x, float y,
                                        uint32_t& h, uint32_t& l) {
    __nv_bfloat16 hx = __float2bfloat16_rn(x);
    __nv_bfloat16 hy = __float2bfloat16_rn(y);
    __nv_bfloat162 hv = __halves2bfloat162(hx, hy);
    h = *(uint32_t*)&hv;
    __nv_bfloat162 lv = __halves2bfloat162(
        __float2bfloat16_rn(x - __bfloat162float(hx)),
        __float2bfloat16_rn(y - __bfloat162float(hy)));
    l = *(uint32_t*)&lv;
}

__device__ __forceinline__ uint32_t f2tf(float x) {
    uint32_t r;
    asm("cvt.rna.tf32.f32 %0, %1;" : "=r"(r) : "f"(x));
    return r;
}

__device__ __forceinline__ void mmab(float (&d)[4], uint4 a, uint2 b) {
    asm volatile(
        "mma.sync.aligned.m16n8k16.row.col.f32.bf16.bf16.f32 "
        "{%0,%1,%2,%3}, {%4,%5,%6,%7}, {%8,%9}, {%0,%1,%2,%3};"
        : "+f"(d[0]), "+f"(d[1]), "+f"(d[2]), "+f"(d[3])
        : "r"(a.x), "r"(a.y), "r"(a.z), "r"(a.w), "r"(b.x), "r"(b.y));
}

__device__ __forceinline__ void mmat(float (&d)[4], uint4 a, uint2 b) {
    asm volatile(
        "mma.sync.aligned.m16n8k8.row.col.f32.tf32.tf32.f32 "
        "{%0,%1,%2,%3}, {%4,%5,%6,%7}, {%8,%9}, {%0,%1,%2,%3};"
        : "+f"(d[0]), "+f"(d[1]), "+f"(d[2]), "+f"(d[3])
        : "r"(a.x), "r"(a.y), "r"(a.z), "r"(a.w), "r"(b.x), "r"(b.y));
}

// Fragment-packed layouts:
//  bf16 A-pack (m16k16): word = ((rb*NKB + kb)*32 + lane)*4 + w
//  bf16 B-pack (n8k16):  word = ((nb*NKB + kb)*32 + lane)*2 + w
//  tf32 B-pack (n8k8):   word = ((nb*NKB8 + kb8)*32 + lane)*2 + w
//    w0=(n=lq, k=la)  w1=(n=lq, k=la+4)

// ===========================================================================
// GEMM: C[128x64] = A[128x768] * W[768x64], bf16x3 (a0b0+a1b0+a0b1).
// 256 threads, 8 warps (4m x 2n of 32x32). BK=16, double-buffered stages.
// (unchanged — R12-proven)
// ===========================================================================
__device__ __forceinline__ void g_loadA(const float* P, float* d) {
    float2 v0 = *(const float2*)P;
    float2 v1 = *(const float2*)(P + 8 * E_);
    float2 v2 = *(const float2*)(P + 8);
    float2 v3 = *(const float2*)(P + 8 * E_ + 8);
    d[0] = v0.x; d[1] = v0.y; d[2] = v1.x; d[3] = v1.y;
    d[4] = v2.x; d[5] = v2.y; d[6] = v3.x; d[7] = v3.y;
}
__device__ __forceinline__ void g_loadB(const float* P, float* d) {
    d[0] = P[0];
    d[1] = P[E_];
    d[2] = P[8 * E_];
    d[3] = P[9 * E_];
}
__device__ __forceinline__ void g_store(uint32_t* sg, int s, int ast, int bst,
                                        const float* a, const float* b) {
    uint32_t* base = sg + s * 3072;
    uint32_t h[4], l[4];
    splitb2(a[0], a[1], h[0], l[0]);
    splitb2(a[2], a[3], h[1], l[1]);
    splitb2(a[4], a[5], h[2], l[2]);
    splitb2(a[6], a[7], h[3], l[3]);
    *(uint4*)(base + ast)        = make_uint4(h[0], h[1], h[2], h[3]);
    *(uint4*)(base + 1024 + ast) = make_uint4(l[0], l[1], l[2], l[3]);
    uint32_t bh0, bl0, bh1, bl1;
    splitb2(b[0], b[1], bh0, bl0);
    splitb2(b[2], b[3], bh1, bl1);
    *(uint2*)(base + 2048 + bst) = make_uint2(bh0, bh1);
    *(uint2*)(base + 2560 + bst) = make_uint2(bl0, bl1);
}

__device__ __forceinline__ void gemm_bf(
    const float* __restrict__ Ag, const float* __restrict__ Wg,
    int m0, int n0, uint32_t* sg, float (&acc)[2][4][4])
{
    const int tid = threadIdx.x, lane = tid & 31, wid = tid >> 5;
    const int rbb = (wid >> 1) * 2, nbb = (wid & 1) * 4;

    const float* Ap = Ag + (size_t)(m0 + (tid >> 5) * 16 + ((lane >> 2))) * E_ + (lane & 3) * 2;
    const float* Wp = Wg + (size_t)((lane & 3) * 2) * E_ + n0 + (tid >> 5) * 8 + (lane >> 2);
    const int ast = tid * 4, bst = tid * 2;

    float ar[2][8], br[2][4];
    g_loadA(Ap, ar[0]);
    g_loadB(Wp, br[0]);
    g_store(sg, 0, ast, bst, ar[0], br[0]);
    g_loadA(Ap + 16, ar[1]);
    g_loadB(Wp + 16 * E_, br[1]);
    __syncthreads();

    #pragma unroll 2
    for (int c = 0; c < 48; c++) {
        const int s = c & 1;
        if (c + 2 < 48) {
            g_loadA(Ap + (c + 2) * 16, ar[s]);
            g_loadB(Wp + (size_t)(c + 2) * 16 * E_, br[s]);
        }
        if (c + 1 < 48)
            g_store(sg, s ^ 1, ast, bst, ar[s ^ 1], br[s ^ 1]);

        uint32_t* AH = sg + s * 3072;
        uint32_t* ALp = AH + 1024;
        uint32_t* BH = AH + 2048;
        uint32_t* BL = AH + 2560;
        uint4 ah0 = *(const uint4*)(AH + (rbb * 32 + lane) * 4);
        uint4 ah1 = *(const uint4*)(AH + ((rbb + 1) * 32 + lane) * 4);
        uint4 al0 = *(const uint4*)(ALp + (rbb * 32 + lane) * 4);
        uint4 al1 = *(const uint4*)(ALp + ((rbb + 1) * 32 + lane) * 4);
        #pragma unroll
        for (int nf = 0; nf < 4; nf++) {
            uint2 bh = *(const uint2*)(BH + ((nbb + nf) * 32 + lane) * 2);
            uint2 bl = *(const uint2*)(BL + ((nbb + nf) * 32 + lane) * 2);
            mmab(acc[0][nf], ah0, bh);
            mmab(acc[0][nf], al0, bh);
            mmab(acc[0][nf], ah0, bl);
            mmab(acc[1][nf], ah1, bh);
            mmab(acc[1][nf], al1, bh);
            mmab(acc[1][nf], ah1, bl);
        }
        __syncthreads();
    }
}

// Projection: out = x@W+b scattered to [B,H,S,D]; z=0 -> Q, z=1 -> K.
__global__ void __launch_bounds__(256, 2) proj_kernel(
    const float* __restrict__ X,
    const float* __restrict__ Wq, const float* __restrict__ bq,
    const float* __restrict__ Wk, const float* __restrict__ bk)
{
    __shared__ uint32_t sg[2 * 3072];

    const float* W    = blockIdx.z ? Wk : Wq;
    const float* bias = blockIdx.z ? bk : bq;
    float* out        = blockIdx.z ? g_K : g_Q;

    const int m0 = blockIdx.x * 128, n0 = blockIdx.y * 64;
    const int lane = threadIdx.x & 31, wid = threadIdx.x >> 5;
    const int wm = (wid >> 1) * 32, wn = (wid & 1) * 32;
    const int la = lane & 3, lq = lane >> 2;

    float acc[2][4][4];
    #pragma unroll
    for (int i = 0; i < 2; i++)
        #pragma unroll
        for (int j = 0; j < 4; j++)
            #pragma unroll
            for (int k = 0; k < 4; k++) acc[i][j][k] = 0.f;

    gemm_bf(X, W, m0, n0, sg, acc);

    #pragma unroll
    for (int mi = 0; mi < 2; mi++) {
        int r = wm + mi * 16 + lq;
        #pragma unroll
        for (int nf = 0; nf < 4; nf++) {
            int n = n0 + wn + nf * 8 + la * 2;
            int h = n / D_, d = n % D_;
            int h1 = (n + 1) / D_, d1 = (n + 1) % D_;
            #pragma unroll
            for (int rr = 0; rr < 2; rr++) {
                int m = m0 + r + rr * 8;
                int bb = m >> 11, s = m & (S_ - 1);
                size_t base = ((size_t)(bb * H_)) * S_ * D_ + (size_t)s * D_;
                out[base + (size_t)h * S_ * D_ + d]   = acc[mi][nf][rr * 2 + 0] + bias[n];
                out[base + (size_t)h1 * S_ * D_ + d1] = acc[mi][nf][rr * 2 + 1] + bias[n + 1];
            }
        }
    }
}

// Output projection: Y = g_AO @ Wo + bo.
__global__ void __launch_bounds__(256, 2) outproj_kernel(
    const float* __restrict__ Wo, const float* __restrict__ bo,
    float* __restrict__ Y)
{
    __shared__ uint32_t sg[2 * 3072];

    const int m0 = blockIdx.x * 128, n0 = blockIdx.y * 64;
    const int lane = threadIdx.x & 31, wid = threadIdx.x >> 5;
    const int wm = (wid >> 1) * 32, wn = (wid & 1) * 32;
    const int la = lane & 3, lq = lane >> 2;

    float acc[2][4][4];
    #pragma unroll
    for (int i = 0; i < 2; i++)
        #pragma unroll
        for (int j = 0; j < 4; j++)
            #pragma unroll
            for (int k = 0; k < 4; k++) acc[i][j][k] = 0.f;

    gemm_bf(g_AO, Wo, m0, n0, sg, acc);

    #pragma unroll
    for (int mi = 0; mi < 2; mi++) {
        int r = wm + mi * 16 + lq;
        #pragma unroll
        for (int nf = 0; nf < 4; nf++) {
            int n = n0 + wn + nf * 8 + la * 2;
            #pragma unroll
            for (int rr = 0; rr < 2; rr++) {
                int m = m0 + r + rr * 8;
                Y[(size_t)m * E_ + n]     = acc[mi][nf][rr * 2 + 0] + bo[n];
                Y[(size_t)m * E_ + n + 1] = acc[mi][nf][rr * 2 + 1] + bo[n + 1];
            }
        }
    }
}

// ===========================================================================
// Flash attention, V == K (reference bug), no-max softmax.
// 16 compute warps: rg=wid&7 (16 rows), cg=wid>>3 (32-key half).
// QK^T: bf16x3 (exponent path). PV: 1xTF32 k8 (value path; proven R10 at
// rel_err 3.44e-4) — P goes exp -> tf32 -> D->A register shuffle, no smem.
// V^T packed once as tf32 k8 B-frags (no hi/lo split).
// Smem words: QsH/QsL 6144 ea | KsH/KsL 3072 ea | Vs 6144 | Ls 256
// ===========================================================================
#define AQ_H 0
#define AQ_L 6144
#define AK_H 12288
#define AK_L 15360
#define AV_  18432
#define AL_  24576
#define ATTN_WORDS (AL_ + 256)
#define ATTN_SMEM_BYTES (ATTN_WORDS * 4)   // 99,328

__global__ void __launch_bounds__(512, 1) attn_kernel()
{
    extern __shared__ uint32_t sm[];
    float* Ls = (float*)(sm + AL_);

    const int tid = threadIdx.x, lane = tid & 31, wid = tid >> 5;
    const int la = lane & 3, lq = lane >> 2;
    const int rg = wid & 7, cg = wid >> 3;
    const int bh = blockIdx.y, qt = blockIdx.x;

    const float* Qg = g_Q + (size_t)bh * S_ * D_ + (size_t)qt * 128 * D_;
    const float* Kg = g_K + (size_t)bh * S_ * D_;

    // ---- pack Q tile (128x96) into hi/lo bf16 A-pack (8 rb x 6 kb16) ----
    #pragma unroll
    for (int i = 0; i < 3; i++) {
        int gg = tid + i * 512;               // < 1536
        int grp = gg >> 5, ln = gg & 31;
        int rb = grp / 6, kb = grp - rb * 6;
        int glq = ln >> 2, gla = ln & 3;
        int r = rb * 16 + glq, c = kb * 16 + gla * 2;
        float2 v0 = *(const float2*)(Qg + r * D_ + c);
        float2 v1 = *(const float2*)(Qg + (r + 8) * D_ + c);
        float2 v2 = *(const float2*)(Qg + r * D_ + c + 8);
        float2 v3 = *(const float2*)(Qg + (r + 8) * D_ + c + 8);
        uint32_t h[4], l[4];
        splitb2(v0.x, v0.y, h[0], l[0]);
        splitb2(v1.x, v1.y, h[1], l[1]);
        splitb2(v2.x, v2.y, h[2], l[2]);
        splitb2(v3.x, v3.y, h[3], l[3]);
        *(uint4*)(sm + AQ_H + gg * 4) = make_uint4(h[0], h[1], h[2], h[3]);
        *(uint4*)(sm + AQ_L + gg * 4) = make_uint4(l[0], l[1], l[2], l[3]);
    }

    // K-pack: 48 groups (8 nb x 6 kb16), warp w -> groups 3w..3w+2
    // V^T-pack: 96 groups (12 nb x 8 kb8), warp w -> groups 6w..6w+5
    int koff[3], voff[6];
    #pragma unroll
    for (int j = 0; j < 3; j++) {
        int g = wid * 3 + j;
        int knb = g / 6, kkb = g - knb * 6;
        koff[j] = (knb * 8 + lq) * D_ + kkb * 16 + la * 2;
    }
    #pragma unroll
    for (int j = 0; j < 6; j++) {
        int g = wid * 6 + j;
        int vnb = g >> 3, vkb = g & 7;             // d-block, key-block of 8
        voff[j] = (vkb * 8 + la) * D_ + vnb * 8 + lq;
    }

    float O[12][4];
    #pragma unroll
    for (int nb = 0; nb < 12; nb++)
        #pragma unroll
        for (int r = 0; r < 4; r++) O[nb][r] = 0.f;
    float ls0 = 0.f, ls1 = 0.f;

    // prefetch tile 0
    float kpr[3][4], vpr[6][2];
    #pragma unroll
    for (int j = 0; j < 3; j++) {
        float2 f0 = *(const float2*)(Kg + koff[j]);
        float2 f1 = *(const float2*)(Kg + koff[j] + 8);
        kpr[j][0] = f0.x; kpr[j][1] = f0.y; kpr[j][2] = f1.x; kpr[j][3] = f1.y;
    }
    #pragma unroll
    for (int j = 0; j < 6; j++) {
        vpr[j][0] = Kg[voff[j]];
        vpr[j][1] = Kg[voff[j] + 4 * D_];
    }

    // D->A shuffle lane constants (tf32 k8 A-frag build)
    const int s0l = (lq << 2) + (la >> 1);
    const int s1l = s0l + 2;
    const bool odd = la & 1;

    for (int kt = 0; kt < 32; kt++) {
        __syncthreads();                       // prev K/V consumed
        // publish K-pack (bf16 hi/lo) + V^T-pack (tf32) from prefetch regs
        #pragma unroll
        for (int j = 0; j < 3; j++) {
            int g = wid * 3 + j;
            uint32_t h0, l0, h1, l1;
            splitb2(kpr[j][0], kpr[j][1], h0, l0);
            splitb2(kpr[j][2], kpr[j][3], h1, l1);
            *(uint2*)(sm + AK_H + (g * 32 + lane) * 2) = make_uint2(h0, h1);
            *(uint2*)(sm + AK_L + (g * 32 + lane) * 2) = make_uint2(l0, l1);
        }
        #pragma unroll
        for (int j = 0; j < 6; j++) {
            int g = wid * 6 + j;
            *(uint2*)(sm + AV_ + (g * 32 + lane) * 2) =
                make_uint2(f2tf(vpr[j][0]), f2tf(vpr[j][1]));
        }
        __syncthreads();

        if (kt < 31) {                         // prefetch next tile
            const float* Kn = Kg + (size_t)(kt + 1) * 64 * D_;
            #pragma unroll
            for (int j = 0; j < 3; j++) {
                float2 f0 = *(const float2*)(Kn + koff[j]);
                float2 f1 = *(const float2*)(Kn + koff[j] + 8);
                kpr[j][0] = f0.x; kpr[j][1] = f0.y;
                kpr[j][2] = f1.x; kpr[j][3] = f1.y;
            }
            #pragma unroll
            for (int j = 0; j < 6; j++) {
                vpr[j][0] = Kn[voff[j]];
                vpr[j][1] = Kn[voff[j] + 4 * D_];
            }
        }

        // S = Q K^T : rows [rg*16,+16) x keys [cg*32,+32), bf16x3
        float s4[4][4];
        #pragma unroll
        for (int nf = 0; nf < 4; nf++)
            #pragma unroll
            for (int k = 0; k < 4; k++) s4[nf][k] = 0.f;

        #pragma unroll
        for (int kb = 0; kb < 6; kb++) {
            uint4 ah = *(const uint4*)(sm + AQ_H + ((rg * 6 + kb) * 32 + lane) * 4);
            uint4 al = *(const uint4*)(sm + AQ_L + ((rg * 6 + kb) * 32 + lane) * 4);
            #pragma unroll
            for (int nf = 0; nf < 4; nf++) {
                int nb = cg * 4 + nf;
                uint2 bhv = *(const uint2*)(sm + AK_H + ((nb * 6 + kb) * 32 + lane) * 2);
                uint2 blv = *(const uint2*)(sm + AK_L + ((nb * 6 + kb) * 32 + lane) * 2);
                mmab(s4[nf], ah, bhv);
                mmab(s4[nf], al, bhv);
                mmab(s4[nf], ah, blv);
            }
        }

        // per 8-key block: exp -> tf32 P (regs) -> D->A shuffle -> PV 1xTF32
        #pragma unroll
        for (int nf = 0; nf < 4; nf++) {
            float p0 = __expf(s4[nf][0]);
            float p1 = __expf(s4[nf][1]);
            float p2 = __expf(s4[nf][2]);
            float p3 = __expf(s4[nf][3]);
            ls0 += p0 + p1;
            ls1 += p2 + p3;
            uint32_t q0 = f2tf(p0), q1 = f2tf(p1), q2 = f2tf(p2), q3 = f2tf(p3);
            uint32_t t0 = __shfl_sync(0xffffffffu, q0, s0l);
            uint32_t t1 = __shfl_sync(0xffffffffu, q1, s0l);
            uint32_t t2 = __shfl_sync(0xffffffffu, q2, s0l);
            uint32_t t3 = __shfl_sync(0xffffffffu, q3, s0l);
            uint32_t u0 = __shfl_sync(0xffffffffu, q0, s1l);
            uint32_t u1 = __shfl_sync(0xffffffffu, q1, s1l);
            uint32_t u2 = __shfl_sync(0xffffffffu, q2, s1l);
            uint32_t u3 = __shfl_sync(0xffffffffu, q3, s1l);
            uint4 a = make_uint4(odd ? t1 : t0, odd ? t3 : t2,
                                 odd ? u1 : u0, odd ? u3 : u2);
            const int kb8 = cg * 4 + nf;       // key-block of 8 within 64
            #pragma unroll
            for (int nb = 0; nb < 12; nb++) {
                uint2 bv = *(const uint2*)(sm + AV_ + ((nb * 8 + kb8) * 32 + lane) * 2);
                mmat(O[nb], a, bv);
            }
        }
    }

    // row sums: quad-lane reduce, then merge cg halves
    ls0 += __shfl_xor_sync(0xffffffffu, ls0, 1);
    ls0 += __shfl_xor_sync(0xffffffffu, ls0, 2);
    ls1 += __shfl_xor_sync(0xffffffffu, ls1, 1);
    ls1 += __shfl_xor_sync(0xffffffffu, ls1, 2);
    const int r0 = rg * 16 + lq;
    if (la == 0) {
        Ls[r0 * 2 + cg]       = ls0;
        Ls[(r0 + 8) * 2 + cg] = ls1;
    }
    __syncthreads();                           // Ls done; Q/K regions dead

    // merge partial O: cg=1 -> smem (stride 97), cg=0 adds + stores
    float* Om = (float*)sm;                    // 128 x 97 floats
    if (cg == 1) {
        #pragma unroll
        for (int nb = 0; nb < 12; nb++) {
            int d = nb * 8 + la * 2;
            Om[r0 * 97 + d]           = O[nb][0];
            Om[r0 * 97 + d + 1]       = O[nb][1];
            Om[(r0 + 8) * 97 + d]     = O[nb][2];
            Om[(r0 + 8) * 97 + d + 1] = O[nb][3];
        }
    }
    __syncthreads();

    if (cg == 0) {
        const float SCALE = 0.10206207261596577f;   // 96^-0.5
        float inv0 = SCALE / (Ls[r0 * 2] + Ls[r0 * 2 + 1]);
        float inv1 = SCALE / (Ls[(r0 + 8) * 2] + Ls[(r0 + 8) * 2 + 1]);
        const int bb = bh >> 3, h = bh & 7;
        int srow0 = qt * 128 + r0;
        float* dst0 = g_AO + ((size_t)(bb * S_ + srow0)) * E_ + h * D_;
        float* dst1 = dst0 + 8 * E_;
        #pragma unroll
        for (int nb = 0; nb < 12; nb++) {
            int d = nb * 8 + la * 2;
            dst0[d]     = (O[nb][0] + Om[r0 * 97 + d])           * inv0;
            dst0[d + 1] = (O[nb][1] + Om[r0 * 97 + d + 1])       * inv0;
            dst1[d]     = (O[nb][2] + Om[(r0 + 8) * 97 + d])     * inv1;
            dst1[d + 1] = (O[nb][3] + Om[(r0 + 8) * 97 + d + 1]) * inv1;
        }
    }
}

// ---------------------------------------------------------------------------
extern "C" void kernel_launch(void* const* d_in, const int* in_sizes, int n_in,
                              void* d_out, int out_size)
{
    const float* x  = (const float*)d_in[0];
    const float* Wq = (const float*)d_in[1];
    const float* bq = (const float*)d_in[2];
    const float* Wk = (const float*)d_in[3];
    const float* bk = (const float*)d_in[4];
    const float* Wo = (const float*)d_in[5];
    const float* bo = (const float*)d_in[6];
    float* out = (float*)d_out;

    cudaFuncSetAttribute(attn_kernel,
                         cudaFuncAttributeMaxDynamicSharedMemorySize,
                         ATTN_SMEM_BYTES);

    proj_kernel<<<dim3(32, 12, 2), 256>>>(x, Wq, bq, Wk, bk);
    attn_kernel<<<dim3(16, 16), 512, ATTN_SMEM_BYTES>>>();
    outproj_kernel<<<dim3(32, 12), 256>>>(Wo, bo, out);
}